// round 4
// baseline (speedup 1.0000x reference)
#include <cuda_runtime.h>
#include <cstdint>

#define N_SAMPLES 131072
#define M_COMP    2048
#define NPAIR     (M_COMP/2)          // 1024 component pairs
#define THREADS   256
#define SAMPLES_PER_BLOCK THREADS                      // 1 sample / thread
#define GRID_MAIN (N_SAMPLES/SAMPLES_PER_BLOCK)        // 512
#define TILE      8                   // pairs per register tile
#define SMEM_BYTES (NPAIR * 3 * 16)   // 48 KB of float4

typedef unsigned long long ull;

// Per-pair coefficient layout (12 floats = 3 float4 per pair), pre-scaled by log2(e):
// [c0e,c0o, c1e,c1o | c2e,c2o, c3e,c3o | c4e,c4o, c5e,c5o]
__device__ float4 g_coef4[NPAIR * 3];

// ---------- packed f32x2 helpers ----------
__device__ __forceinline__ ull pk2(float x) {
    ull r; asm("mov.b64 %0,{%1,%1};" : "=l"(r) : "f"(x)); return r;
}
__device__ __forceinline__ ull pk2p(float lo, float hi) {
    ull r; asm("mov.b64 %0,{%1,%2};" : "=l"(r) : "f"(lo), "f"(hi)); return r;
}
__device__ __forceinline__ void unpk(ull v, float& lo, float& hi) {
    asm("mov.b64 {%0,%1},%2;" : "=f"(lo), "=f"(hi) : "l"(v));
}
__device__ __forceinline__ ull f2fma(ull a, ull b, ull c) {
    ull d; asm("fma.rn.f32x2 %0,%1,%2,%3;" : "=l"(d) : "l"(a), "l"(b), "l"(c)); return d;
}
__device__ __forceinline__ ull f2add(ull a, ull b) {
    ull d; asm("add.rn.f32x2 %0,%1,%2;" : "=l"(d) : "l"(a), "l"(b)); return d;
}
__device__ __forceinline__ float ex2(float x) {
    float y; asm("ex2.approx.ftz.f32 %0,%1;" : "=f"(y) : "f"(x)); return y;
}
__device__ __forceinline__ float lg2(float x) {
    float y; asm("lg2.approx.f32 %0,%1;" : "=f"(y) : "f"(x)); return y;
}
__device__ __forceinline__ void lds2(ull& a, ull& b, uint32_t addr) {
    asm("ld.shared.v2.b64 {%0,%1},[%2];" : "=l"(a), "=l"(b) : "r"(addr));
}

// ---------- fused prologue: logsumexp(w) + per-component coefficients ----------
__device__ __forceinline__ void write_coef(int m, float lse,
                                           const float* mu, const float* Am,
                                           float wm) {
    float a00 = Am[4*m+0], a01 = Am[4*m+1], a10 = Am[4*m+2], a11 = Am[4*m+3];
    float g00 = 0.5f * (a00*a00 + a01*a01);
    float g01 = 0.5f * (a00*a10 + a01*a11);
    float g11 = 0.5f * (a10*a10 + a11*a11);
    float gs  = 2.0f * g01;
    float det = g00*g11 - g01*g01;
    float wl  = (wm - lse) + 0.5f * logf(det);
    float m0 = mu[2*m], m1 = mu[2*m+1];
    float c0 = -g00, c1 = -gs, c2 = -g11;
    float c3 = 2.0f*g00*m0 + gs*m1;
    float c4 = gs*m0 + 2.0f*g11*m1;
    float c5 = wl - (g00*m0*m0 + gs*m0*m1 + g11*m1*m1);
    const float L = 1.4426950408889634f; // log2(e)
    float* o = (float*)g_coef4;
    int p = m >> 1, off = (m & 1);
    int b = p * 12 + off;
    o[b + 0]  = c0 * L;
    o[b + 2]  = c1 * L;
    o[b + 4]  = c2 * L;
    o[b + 6]  = c3 * L;
    o[b + 8]  = c4 * L;
    o[b + 10] = c5 * L;
}

__global__ void gm_prep_kernel(const float* __restrict__ w,
                               const float* __restrict__ mu,
                               const float* __restrict__ Am) {
    __shared__ float red[32];
    __shared__ float s_mx, s_lse;
    int t = threadIdx.x;
    int lane = t & 31, wid = t >> 5;

    float a = w[t], b = w[t + 1024];

    // block max via shfl + one warp
    float v = fmaxf(a, b);
    #pragma unroll
    for (int o = 16; o; o >>= 1) v = fmaxf(v, __shfl_xor_sync(0xffffffffu, v, o));
    if (lane == 0) red[wid] = v;
    __syncthreads();
    if (wid == 0) {
        float m = red[lane];
        #pragma unroll
        for (int o = 16; o; o >>= 1) m = fmaxf(m, __shfl_xor_sync(0xffffffffu, m, o));
        if (lane == 0) s_mx = m;
    }
    __syncthreads();
    float mx = s_mx;

    // block sum of exp via shfl + one warp
    float e = expf(a - mx) + expf(b - mx);
    #pragma unroll
    for (int o = 16; o; o >>= 1) e += __shfl_xor_sync(0xffffffffu, e, o);
    __syncthreads();   // red reuse
    if (lane == 0) red[wid] = e;
    __syncthreads();
    if (wid == 0) {
        float s = red[lane];
        #pragma unroll
        for (int o = 16; o; o >>= 1) s += __shfl_xor_sync(0xffffffffu, s, o);
        if (lane == 0) s_lse = mx + logf(s);
    }
    __syncthreads();
    float lse = s_lse;

    write_coef(t, lse, mu, Am, a);
    write_coef(t + 1024, lse, mu, Am, b);
}

// ---------- main: 1 sample/thread, register-tiled online logsumexp ----------
__global__ __launch_bounds__(THREADS, 4) void gm_main_kernel(
    const float* __restrict__ sample, float* __restrict__ out) {
    extern __shared__ float4 sc[];     // 48 KB dynamic
    #pragma unroll 1
    for (int i = threadIdx.x; i < NPAIR * 3; i += THREADS)
        sc[i] = g_coef4[i];
    __syncthreads();
    uint32_t sbase = (uint32_t)__cvta_generic_to_shared(sc);

    int n = blockIdx.x * SAMPLES_PER_BLOCK + threadIdx.x;
    float2 p = ((const float2*)sample)[n];

    // packed features (dup in both halves): [x0^2, x0x1, x1^2, x0, x1]
    ull F0 = pk2(p.x * p.x), F1 = pk2(p.x * p.y), F2 = pk2(p.y * p.y);
    ull X0 = pk2(p.x), X1 = pk2(p.y);

    float ma0 = -3.0e38f, ma1 = -3.0e38f;
    ull SA = 0ull;                     // packed f32x2 running sum

    for (int t = 0; t < NPAIR; t += TILE) {
        ull va[TILE];
        float ta0 = -3.0e38f, ta1 = -3.0e38f;
        uint32_t base = sbase + (uint32_t)t * 48u;
        #pragma unroll
        for (int i = 0; i < TILE; ++i) {
            uint32_t a = base + (uint32_t)i * 48u;
            ull C0, C1, C2, C3, C4, C5;
            lds2(C0, C1, a);
            lds2(C2, C3, a + 16u);
            lds2(C4, C5, a + 32u);
            va[i] = f2fma(F0, C0, f2fma(F1, C1, f2fma(F2, C2,
                    f2fma(X0, C3, f2fma(X1, C4, C5)))));
            float x, y;
            unpk(va[i], x, y); ta0 = fmaxf(ta0, x); ta1 = fmaxf(ta1, y);
        }
        float na0 = fmaxf(ma0, ta0), na1 = fmaxf(ma1, ta1);
        ull RA  = pk2p(ex2(ma0 - na0), ex2(ma1 - na1));
        ull NMA = pk2p(-na0, -na1);
        ull TSA = 0ull;
        #pragma unroll
        for (int i = 0; i < TILE; ++i) {
            ull da = f2add(va[i], NMA);
            float x, y;
            unpk(da, x, y);
            TSA = f2add(TSA, pk2p(ex2(x), ex2(y)));
        }
        SA = f2fma(SA, RA, TSA);
        ma0 = na0; ma1 = na1;
    }

    const float LN2 = 0.6931471805599453f;
    float s0, s1;
    unpk(SA, s0, s1);
    float M = fmaxf(ma0, ma1);
    float tot = s0 * ex2(ma0 - M) + s1 * ex2(ma1 - M);
    out[n] = (M + lg2(tot)) * LN2;
}

extern "C" void kernel_launch(void* const* d_in, const int* in_sizes, int n_in,
                              void* d_out, int out_size) {
    // Resolve inputs by element count (sample=262144, mu=4096, A=8192, w=2048)
    const float *sample = nullptr, *mu = nullptr, *A = nullptr, *w = nullptr;
    for (int i = 0; i < n_in; ++i) {
        int sz = in_sizes[i];
        const float* p = (const float*)d_in[i];
        if      (sz == N_SAMPLES * 2) sample = p;
        else if (sz == M_COMP * 2)    mu = p;
        else if (sz == M_COMP * 4)    A = p;
        else if (sz == M_COMP)        w = p;
    }
    // Opt in to 48KB dynamic smem and max smem carveout so 4 CTAs/SM fit.
    cudaFuncSetAttribute(gm_main_kernel,
                         cudaFuncAttributeMaxDynamicSharedMemorySize, SMEM_BYTES);
    cudaFuncSetAttribute(gm_main_kernel,
                         cudaFuncAttributePreferredSharedMemoryCarveout, 100);
    gm_prep_kernel<<<1, 1024>>>(w, mu, A);
    gm_main_kernel<<<GRID_MAIN, THREADS, SMEM_BYTES>>>(sample, (float*)d_out);
}

// round 5
// speedup vs baseline: 1.1332x; 1.1332x over previous
#include <cuda_runtime.h>
#include <cstdint>

#define N_SAMPLES 131072
#define M_COMP    2048
#define NPAIR     (M_COMP/2)          // 1024 component pairs
#define THREADS   128
#define SPT       2                   // samples per thread
#define SAMPLES_PER_BLOCK (THREADS*SPT)                 // 256
#define GRID_MAIN (N_SAMPLES/SAMPLES_PER_BLOCK)         // 512
#define TILE      8                   // pairs per register tile
#define SMEM_BYTES (NPAIR * 3 * 16)   // 48 KB of float4

typedef unsigned long long ull;

// Per-pair coefficient layout (12 floats = 3 float4 per pair), pre-scaled by log2(e):
// [c0e,c0o, c1e,c1o | c2e,c2o, c3e,c3o | c4e,c4o, c5e,c5o]
__device__ float4 g_coef4[NPAIR * 3];

// ---------- packed f32x2 helpers ----------
__device__ __forceinline__ ull pk2(float x) {
    ull r; asm("mov.b64 %0,{%1,%1};" : "=l"(r) : "f"(x)); return r;
}
__device__ __forceinline__ ull pk2p(float lo, float hi) {
    ull r; asm("mov.b64 %0,{%1,%2};" : "=l"(r) : "f"(lo), "f"(hi)); return r;
}
__device__ __forceinline__ void unpk(ull v, float& lo, float& hi) {
    asm("mov.b64 {%0,%1},%2;" : "=f"(lo), "=f"(hi) : "l"(v));
}
__device__ __forceinline__ ull f2fma(ull a, ull b, ull c) {
    ull d; asm("fma.rn.f32x2 %0,%1,%2,%3;" : "=l"(d) : "l"(a), "l"(b), "l"(c)); return d;
}
__device__ __forceinline__ ull f2add(ull a, ull b) {
    ull d; asm("add.rn.f32x2 %0,%1,%2;" : "=l"(d) : "l"(a), "l"(b)); return d;
}
__device__ __forceinline__ float ex2(float x) {
    float y; asm("ex2.approx.ftz.f32 %0,%1;" : "=f"(y) : "f"(x)); return y;
}
__device__ __forceinline__ float lg2(float x) {
    float y; asm("lg2.approx.f32 %0,%1;" : "=f"(y) : "f"(x)); return y;
}
__device__ __forceinline__ void lds2(ull& a, ull& b, uint32_t addr) {
    asm("ld.shared.v2.b64 {%0,%1},[%2];" : "=l"(a), "=l"(b) : "r"(addr));
}

// ---------- fused prologue: logsumexp(w) + per-component coefficients ----------
__device__ __forceinline__ void write_coef(int m, float lse,
                                           const float* mu, const float* Am,
                                           float wm) {
    float a00 = Am[4*m+0], a01 = Am[4*m+1], a10 = Am[4*m+2], a11 = Am[4*m+3];
    float g00 = 0.5f * (a00*a00 + a01*a01);
    float g01 = 0.5f * (a00*a10 + a01*a11);
    float g11 = 0.5f * (a10*a10 + a11*a11);
    float gs  = 2.0f * g01;
    float det = g00*g11 - g01*g01;
    float wl  = (wm - lse) + 0.5f * logf(det);
    float m0 = mu[2*m], m1 = mu[2*m+1];
    float c0 = -g00, c1 = -gs, c2 = -g11;
    float c3 = 2.0f*g00*m0 + gs*m1;
    float c4 = gs*m0 + 2.0f*g11*m1;
    float c5 = wl - (g00*m0*m0 + gs*m0*m1 + g11*m1*m1);
    const float L = 1.4426950408889634f; // log2(e)
    float* o = (float*)g_coef4;
    int p = m >> 1, off = (m & 1);
    int b = p * 12 + off;
    o[b + 0]  = c0 * L;
    o[b + 2]  = c1 * L;
    o[b + 4]  = c2 * L;
    o[b + 6]  = c3 * L;
    o[b + 8]  = c4 * L;
    o[b + 10] = c5 * L;
}

__global__ void gm_prep_kernel(const float* __restrict__ w,
                               const float* __restrict__ mu,
                               const float* __restrict__ Am) {
    __shared__ float red[32];
    __shared__ float s_mx, s_lse;
    int t = threadIdx.x;
    int lane = t & 31, wid = t >> 5;

    float a = w[t], b = w[t + 1024];

    float v = fmaxf(a, b);
    #pragma unroll
    for (int o = 16; o; o >>= 1) v = fmaxf(v, __shfl_xor_sync(0xffffffffu, v, o));
    if (lane == 0) red[wid] = v;
    __syncthreads();
    if (wid == 0) {
        float m = red[lane];
        #pragma unroll
        for (int o = 16; o; o >>= 1) m = fmaxf(m, __shfl_xor_sync(0xffffffffu, m, o));
        if (lane == 0) s_mx = m;
    }
    __syncthreads();
    float mx = s_mx;

    float e = expf(a - mx) + expf(b - mx);
    #pragma unroll
    for (int o = 16; o; o >>= 1) e += __shfl_xor_sync(0xffffffffu, e, o);
    __syncthreads();
    if (lane == 0) red[wid] = e;
    __syncthreads();
    if (wid == 0) {
        float s = red[lane];
        #pragma unroll
        for (int o = 16; o; o >>= 1) s += __shfl_xor_sync(0xffffffffu, s, o);
        if (lane == 0) s_lse = mx + logf(s);
    }
    __syncthreads();
    float lse = s_lse;

    write_coef(t, lse, mu, Am, a);
    write_coef(t + 1024, lse, mu, Am, b);
}

// ---------- main: 2 samples/thread, register-tiled online logsumexp ----------
__global__ __launch_bounds__(THREADS, 4) void gm_main_kernel(
    const float* __restrict__ sample, float* __restrict__ out) {
    extern __shared__ float4 sc[];     // 48 KB dynamic
    #pragma unroll 1
    for (int i = threadIdx.x; i < NPAIR * 3; i += THREADS)
        sc[i] = g_coef4[i];
    __syncthreads();
    uint32_t sbase = (uint32_t)__cvta_generic_to_shared(sc);

    int n0 = blockIdx.x * SAMPLES_PER_BLOCK + threadIdx.x;
    int n1 = n0 + THREADS;
    const float2* sp = (const float2*)sample;
    float2 pa = sp[n0];
    float2 pb = sp[n1];

    // packed features (dup in both halves): [x0^2, x0x1, x1^2, x0, x1]
    ull AF0 = pk2(pa.x * pa.x), AF1 = pk2(pa.x * pa.y), AF2 = pk2(pa.y * pa.y);
    ull AX0 = pk2(pa.x), AX1 = pk2(pa.y);
    ull BF0 = pk2(pb.x * pb.x), BF1 = pk2(pb.x * pb.y), BF2 = pk2(pb.y * pb.y);
    ull BX0 = pk2(pb.x), BX1 = pk2(pb.y);

    float ma0 = -3.0e38f, ma1 = -3.0e38f, mb0 = -3.0e38f, mb1 = -3.0e38f;
    ull SA = 0ull, SB = 0ull;

    for (int t = 0; t < NPAIR; t += TILE) {
        ull va[TILE], vb[TILE];
        float ta0 = -3.0e38f, ta1 = -3.0e38f, tb0 = -3.0e38f, tb1 = -3.0e38f;
        uint32_t base = sbase + (uint32_t)t * 48u;
        #pragma unroll
        for (int i = 0; i < TILE; ++i) {
            uint32_t a = base + (uint32_t)i * 48u;
            ull C0, C1, C2, C3, C4, C5;
            lds2(C0, C1, a);
            lds2(C2, C3, a + 16u);
            lds2(C4, C5, a + 32u);
            va[i] = f2fma(AF0, C0, f2fma(AF1, C1, f2fma(AF2, C2,
                    f2fma(AX0, C3, f2fma(AX1, C4, C5)))));
            vb[i] = f2fma(BF0, C0, f2fma(BF1, C1, f2fma(BF2, C2,
                    f2fma(BX0, C3, f2fma(BX1, C4, C5)))));
            float x, y;
            unpk(va[i], x, y); ta0 = fmaxf(ta0, x); ta1 = fmaxf(ta1, y);
            unpk(vb[i], x, y); tb0 = fmaxf(tb0, x); tb1 = fmaxf(tb1, y);
        }
        float na0 = fmaxf(ma0, ta0), na1 = fmaxf(ma1, ta1);
        float nb0 = fmaxf(mb0, tb0), nb1 = fmaxf(mb1, tb1);
        ull RA  = pk2p(ex2(ma0 - na0), ex2(ma1 - na1));
        ull RB  = pk2p(ex2(mb0 - nb0), ex2(mb1 - nb1));
        ull NMA = pk2p(-na0, -na1);
        ull NMB = pk2p(-nb0, -nb1);
        ull TSA = 0ull, TSB = 0ull;
        #pragma unroll
        for (int i = 0; i < TILE; ++i) {
            ull da = f2add(va[i], NMA);
            ull db = f2add(vb[i], NMB);
            float x, y;
            unpk(da, x, y);
            TSA = f2add(TSA, pk2p(ex2(x), ex2(y)));
            unpk(db, x, y);
            TSB = f2add(TSB, pk2p(ex2(x), ex2(y)));
        }
        SA = f2fma(SA, RA, TSA);
        SB = f2fma(SB, RB, TSB);
        ma0 = na0; ma1 = na1; mb0 = nb0; mb1 = nb1;
    }

    const float LN2 = 0.6931471805599453f;
    float s0, s1;
    unpk(SA, s0, s1);
    {
        float M = fmaxf(ma0, ma1);
        float tot = s0 * ex2(ma0 - M) + s1 * ex2(ma1 - M);
        out[n0] = (M + lg2(tot)) * LN2;
    }
    unpk(SB, s0, s1);
    {
        float M = fmaxf(mb0, mb1);
        float tot = s0 * ex2(mb0 - M) + s1 * ex2(mb1 - M);
        out[n1] = (M + lg2(tot)) * LN2;
    }
}

extern "C" void kernel_launch(void* const* d_in, const int* in_sizes, int n_in,
                              void* d_out, int out_size) {
    // Resolve inputs by element count (sample=262144, mu=4096, A=8192, w=2048)
    const float *sample = nullptr, *mu = nullptr, *A = nullptr, *w = nullptr;
    for (int i = 0; i < n_in; ++i) {
        int sz = in_sizes[i];
        const float* p = (const float*)d_in[i];
        if      (sz == N_SAMPLES * 2) sample = p;
        else if (sz == M_COMP * 2)    mu = p;
        else if (sz == M_COMP * 4)    A = p;
        else if (sz == M_COMP)        w = p;
    }
    // 48KB dynamic smem + full carveout so 4 CTAs/SM (192KB smem) fit.
    cudaFuncSetAttribute(gm_main_kernel,
                         cudaFuncAttributeMaxDynamicSharedMemorySize, SMEM_BYTES);
    cudaFuncSetAttribute(gm_main_kernel,
                         cudaFuncAttributePreferredSharedMemoryCarveout, 100);
    gm_prep_kernel<<<1, 1024>>>(w, mu, A);
    gm_main_kernel<<<GRID_MAIN, THREADS, SMEM_BYTES>>>(sample, (float*)d_out);
}

// round 6
// speedup vs baseline: 1.5893x; 1.4025x over previous
#include <cuda_runtime.h>
#include <cstdint>

#define N_SAMPLES 131072
#define M_COMP    2048
#define NPAIR     (M_COMP/2)          // 1024 component pairs
#define THREADS   128
#define SPT       2
#define SAMPLES_PER_BLOCK (THREADS*SPT)                 // 256
#define GRID_MAIN (N_SAMPLES/SAMPLES_PER_BLOCK)         // 512
#define TILE      8
#define SMEM_BYTES (NPAIR * 3 * 16)   // 48 KB (general-path layout; fast uses 32 KB)

typedef unsigned long long ull;

// general path: per pair 12 floats [c0e,c0o,c1e,c1o | c2e,c2o,c3e,c3o | c4e,c4o,c5e,c5o] (x log2e)
__device__ float4 g_coef4[NPAIR * 3];
// fast path: per pair 8 floats [c3e,c3o, c4e,c4o, c5e,c5o, pad,pad] (x log2e)
__device__ float4 g_fastc[NPAIR * 2];
// L*g00, L*gs, L*g11 of component 0 (valid when uniform)
__device__ float  g_quad[4];
__device__ int    g_uniform;

// ---------- packed f32x2 helpers ----------
__device__ __forceinline__ ull pk2(float x) {
    ull r; asm("mov.b64 %0,{%1,%1};" : "=l"(r) : "f"(x)); return r;
}
__device__ __forceinline__ ull pk2p(float lo, float hi) {
    ull r; asm("mov.b64 %0,{%1,%2};" : "=l"(r) : "f"(lo), "f"(hi)); return r;
}
__device__ __forceinline__ void unpk(ull v, float& lo, float& hi) {
    asm("mov.b64 {%0,%1},%2;" : "=f"(lo), "=f"(hi) : "l"(v));
}
__device__ __forceinline__ ull f2fma(ull a, ull b, ull c) {
    ull d; asm("fma.rn.f32x2 %0,%1,%2,%3;" : "=l"(d) : "l"(a), "l"(b), "l"(c)); return d;
}
__device__ __forceinline__ ull f2add(ull a, ull b) {
    ull d; asm("add.rn.f32x2 %0,%1,%2;" : "=l"(d) : "l"(a), "l"(b)); return d;
}
__device__ __forceinline__ float ex2(float x) {
    float y; asm("ex2.approx.ftz.f32 %0,%1;" : "=f"(y) : "f"(x)); return y;
}
__device__ __forceinline__ float lg2(float x) {
    float y; asm("lg2.approx.f32 %0,%1;" : "=f"(y) : "f"(x)); return y;
}
__device__ __forceinline__ void lds2(ull& a, ull& b, uint32_t addr) {
    asm("ld.shared.v2.b64 {%0,%1},[%2];" : "=l"(a), "=l"(b) : "r"(addr));
}
__device__ __forceinline__ ull ldsb64(uint32_t addr) {
    ull a; asm("ld.shared.b64 %0,[%1];" : "=l"(a) : "r"(addr)); return a;
}

// ---------- prologue: logsumexp(w) + coefficients + uniformity flag ----------
__device__ __forceinline__ void write_coef(int m, float lse,
                                           const float* mu, const float* Am,
                                           float wm,
                                           float g000, float g010, float g110,
                                           int* flag) {
    float a00 = Am[4*m+0], a01 = Am[4*m+1], a10 = Am[4*m+2], a11 = Am[4*m+3];
    float g00 = 0.5f * (a00*a00 + a01*a01);
    float g01 = 0.5f * (a00*a10 + a01*a11);
    float g11 = 0.5f * (a10*a10 + a11*a11);
    if (!(g00 == g000 && g01 == g010 && g11 == g110))
        atomicAnd(flag, 0);
    float gs  = 2.0f * g01;
    float det = g00*g11 - g01*g01;
    float wl  = (wm - lse) + 0.5f * logf(det);
    float m0 = mu[2*m], m1 = mu[2*m+1];
    float c0 = -g00, c1 = -gs, c2 = -g11;
    float c3 = 2.0f*g00*m0 + gs*m1;
    float c4 = gs*m0 + 2.0f*g11*m1;
    float c5 = wl - (g00*m0*m0 + gs*m0*m1 + g11*m1*m1);
    const float L = 1.4426950408889634f; // log2(e)
    int p = m >> 1, off = (m & 1);
    float* o = (float*)g_coef4;
    int b = p * 12 + off;
    o[b + 0]  = c0 * L;
    o[b + 2]  = c1 * L;
    o[b + 4]  = c2 * L;
    o[b + 6]  = c3 * L;
    o[b + 8]  = c4 * L;
    o[b + 10] = c5 * L;
    float* f = (float*)g_fastc;
    int b2 = p * 8 + off;
    f[b2 + 0] = c3 * L;
    f[b2 + 2] = c4 * L;
    f[b2 + 4] = c5 * L;
}

__global__ void gm_prep_kernel(const float* __restrict__ w,
                               const float* __restrict__ mu,
                               const float* __restrict__ Am) {
    __shared__ float red[32];
    __shared__ float s_mx, s_lse;
    __shared__ int s_flag;
    int t = threadIdx.x;
    int lane = t & 31, wid = t >> 5;
    if (t == 0) s_flag = 1;

    float a = w[t], b = w[t + 1024];

    float v = fmaxf(a, b);
    #pragma unroll
    for (int o = 16; o; o >>= 1) v = fmaxf(v, __shfl_xor_sync(0xffffffffu, v, o));
    if (lane == 0) red[wid] = v;
    __syncthreads();
    if (wid == 0) {
        float m = red[lane];
        #pragma unroll
        for (int o = 16; o; o >>= 1) m = fmaxf(m, __shfl_xor_sync(0xffffffffu, m, o));
        if (lane == 0) s_mx = m;
    }
    __syncthreads();
    float mx = s_mx;

    float e = expf(a - mx) + expf(b - mx);
    #pragma unroll
    for (int o = 16; o; o >>= 1) e += __shfl_xor_sync(0xffffffffu, e, o);
    __syncthreads();
    if (lane == 0) red[wid] = e;
    __syncthreads();
    if (wid == 0) {
        float s = red[lane];
        #pragma unroll
        for (int o = 16; o; o >>= 1) s += __shfl_xor_sync(0xffffffffu, s, o);
        if (lane == 0) s_lse = mx + logf(s);
    }
    __syncthreads();
    float lse = s_lse;

    // component-0 reference G for uniformity check
    float r00 = Am[0], r01 = Am[1], r10 = Am[2], r11 = Am[3];
    float g000 = 0.5f * (r00*r00 + r01*r01);
    float g010 = 0.5f * (r00*r10 + r01*r11);
    float g110 = 0.5f * (r10*r10 + r11*r11);

    write_coef(t,        lse, mu, Am, a, g000, g010, g110, &s_flag);
    write_coef(t + 1024, lse, mu, Am, b, g000, g010, g110, &s_flag);
    __syncthreads();
    if (t == 0) {
        g_uniform = s_flag;
        const float L = 1.4426950408889634f;
        g_quad[0] = g000 * L;
        g_quad[1] = 2.0f * g010 * L;
        g_quad[2] = g110 * L;
    }
}

// ---------- main ----------
__global__ __launch_bounds__(THREADS, 4) void gm_main_kernel(
    const float* __restrict__ sample, float* __restrict__ out) {
    extern __shared__ float4 sc[];   // 48 KB dynamic (fast path uses 32 KB)
    const float LN2 = 0.6931471805599453f;

    int n0 = blockIdx.x * SAMPLES_PER_BLOCK + threadIdx.x;
    int n1 = n0 + THREADS;
    const float2* sp = (const float2*)sample;
    float2 pa = sp[n0];
    float2 pb = sp[n1];

    int uni = g_uniform;   // grid-uniform branch

    if (uni) {
        // ================= FAST PATH: uniform covariance =================
        #pragma unroll 1
        for (int i = threadIdx.x; i < NPAIR * 2; i += THREADS)
            sc[i] = g_fastc[i];
        __syncthreads();
        uint32_t sbase = (uint32_t)__cvta_generic_to_shared(sc);

        float q00 = g_quad[0], qs = g_quad[1], q11 = g_quad[2];
        // per-sample constants (log2 domain): K = -(g00 x0^2 + gs x0 x1 + g11 x1^2)*L
        float KA = -(q00*pa.x*pa.x + qs*pa.x*pa.y + q11*pa.y*pa.y);
        float KB = -(q00*pb.x*pb.x + qs*pb.x*pb.y + q11*pb.y*pb.y);

        ull AX0 = pk2(pa.x), AX1 = pk2(pa.y);
        ull BX0 = pk2(pb.x), BX1 = pk2(pb.y);

        float ma0 = -3.0e38f, ma1 = -3.0e38f, mb0 = -3.0e38f, mb1 = -3.0e38f;
        ull SA = 0ull, SB = 0ull;

        for (int t = 0; t < NPAIR; t += TILE) {
            ull va[TILE], vb[TILE];
            float ta0 = -3.0e38f, ta1 = -3.0e38f, tb0 = -3.0e38f, tb1 = -3.0e38f;
            uint32_t base = sbase + (uint32_t)t * 32u;
            #pragma unroll
            for (int i = 0; i < TILE; ++i) {
                uint32_t a = base + (uint32_t)i * 32u;
                ull U0, U1;
                lds2(U0, U1, a);
                ull U2 = ldsb64(a + 16u);
                va[i] = f2fma(AX0, U0, f2fma(AX1, U1, U2));
                vb[i] = f2fma(BX0, U0, f2fma(BX1, U1, U2));
                float x, y;
                unpk(va[i], x, y); ta0 = fmaxf(ta0, x); ta1 = fmaxf(ta1, y);
                unpk(vb[i], x, y); tb0 = fmaxf(tb0, x); tb1 = fmaxf(tb1, y);
            }
            float na0 = fmaxf(ma0, ta0), na1 = fmaxf(ma1, ta1);
            float nb0 = fmaxf(mb0, tb0), nb1 = fmaxf(mb1, tb1);
            ull RA  = pk2p(ex2(ma0 - na0), ex2(ma1 - na1));
            ull RB  = pk2p(ex2(mb0 - nb0), ex2(mb1 - nb1));
            ull NMA = pk2p(-na0, -na1);
            ull NMB = pk2p(-nb0, -nb1);
            ull TSA = 0ull, TSB = 0ull;
            #pragma unroll
            for (int i = 0; i < TILE; ++i) {
                ull da = f2add(va[i], NMA);
                ull db = f2add(vb[i], NMB);
                float x, y;
                unpk(da, x, y);
                TSA = f2add(TSA, pk2p(ex2(x), ex2(y)));
                unpk(db, x, y);
                TSB = f2add(TSB, pk2p(ex2(x), ex2(y)));
            }
            SA = f2fma(SA, RA, TSA);
            SB = f2fma(SB, RB, TSB);
            ma0 = na0; ma1 = na1; mb0 = nb0; mb1 = nb1;
        }

        float s0, s1;
        unpk(SA, s0, s1);
        {
            float M = fmaxf(ma0, ma1);
            float tot = s0 * ex2(ma0 - M) + s1 * ex2(ma1 - M);
            out[n0] = (KA + M + lg2(tot)) * LN2;
        }
        unpk(SB, s0, s1);
        {
            float M = fmaxf(mb0, mb1);
            float tot = s0 * ex2(mb0 - M) + s1 * ex2(mb1 - M);
            out[n1] = (KB + M + lg2(tot)) * LN2;
        }
    } else {
        // ================= GENERAL PATH (round-5, proven) =================
        #pragma unroll 1
        for (int i = threadIdx.x; i < NPAIR * 3; i += THREADS)
            sc[i] = g_coef4[i];
        __syncthreads();
        uint32_t sbase = (uint32_t)__cvta_generic_to_shared(sc);

        ull AF0 = pk2(pa.x * pa.x), AF1 = pk2(pa.x * pa.y), AF2 = pk2(pa.y * pa.y);
        ull AX0 = pk2(pa.x), AX1 = pk2(pa.y);
        ull BF0 = pk2(pb.x * pb.x), BF1 = pk2(pb.x * pb.y), BF2 = pk2(pb.y * pb.y);
        ull BX0 = pk2(pb.x), BX1 = pk2(pb.y);

        float ma0 = -3.0e38f, ma1 = -3.0e38f, mb0 = -3.0e38f, mb1 = -3.0e38f;
        ull SA = 0ull, SB = 0ull;

        for (int t = 0; t < NPAIR; t += TILE) {
            ull va[TILE], vb[TILE];
            float ta0 = -3.0e38f, ta1 = -3.0e38f, tb0 = -3.0e38f, tb1 = -3.0e38f;
            uint32_t base = sbase + (uint32_t)t * 48u;
            #pragma unroll
            for (int i = 0; i < TILE; ++i) {
                uint32_t a = base + (uint32_t)i * 48u;
                ull C0, C1, C2, C3, C4, C5;
                lds2(C0, C1, a);
                lds2(C2, C3, a + 16u);
                lds2(C4, C5, a + 32u);
                va[i] = f2fma(AF0, C0, f2fma(AF1, C1, f2fma(AF2, C2,
                        f2fma(AX0, C3, f2fma(AX1, C4, C5)))));
                vb[i] = f2fma(BF0, C0, f2fma(BF1, C1, f2fma(BF2, C2,
                        f2fma(BX0, C3, f2fma(BX1, C4, C5)))));
                float x, y;
                unpk(va[i], x, y); ta0 = fmaxf(ta0, x); ta1 = fmaxf(ta1, y);
                unpk(vb[i], x, y); tb0 = fmaxf(tb0, x); tb1 = fmaxf(tb1, y);
            }
            float na0 = fmaxf(ma0, ta0), na1 = fmaxf(ma1, ta1);
            float nb0 = fmaxf(mb0, tb0), nb1 = fmaxf(mb1, tb1);
            ull RA  = pk2p(ex2(ma0 - na0), ex2(ma1 - na1));
            ull RB  = pk2p(ex2(mb0 - nb0), ex2(mb1 - nb1));
            ull NMA = pk2p(-na0, -na1);
            ull NMB = pk2p(-nb0, -nb1);
            ull TSA = 0ull, TSB = 0ull;
            #pragma unroll
            for (int i = 0; i < TILE; ++i) {
                ull da = f2add(va[i], NMA);
                ull db = f2add(vb[i], NMB);
                float x, y;
                unpk(da, x, y);
                TSA = f2add(TSA, pk2p(ex2(x), ex2(y)));
                unpk(db, x, y);
                TSB = f2add(TSB, pk2p(ex2(x), ex2(y)));
            }
            SA = f2fma(SA, RA, TSA);
            SB = f2fma(SB, RB, TSB);
            ma0 = na0; ma1 = na1; mb0 = nb0; mb1 = nb1;
        }

        float s0, s1;
        unpk(SA, s0, s1);
        {
            float M = fmaxf(ma0, ma1);
            float tot = s0 * ex2(ma0 - M) + s1 * ex2(ma1 - M);
            out[n0] = (M + lg2(tot)) * LN2;
        }
        unpk(SB, s0, s1);
        {
            float M = fmaxf(mb0, mb1);
            float tot = s0 * ex2(mb0 - M) + s1 * ex2(mb1 - M);
            out[n1] = (M + lg2(tot)) * LN2;
        }
    }
}

extern "C" void kernel_launch(void* const* d_in, const int* in_sizes, int n_in,
                              void* d_out, int out_size) {
    const float *sample = nullptr, *mu = nullptr, *A = nullptr, *w = nullptr;
    for (int i = 0; i < n_in; ++i) {
        int sz = in_sizes[i];
        const float* p = (const float*)d_in[i];
        if      (sz == N_SAMPLES * 2) sample = p;
        else if (sz == M_COMP * 2)    mu = p;
        else if (sz == M_COMP * 4)    A = p;
        else if (sz == M_COMP)        w = p;
    }
    cudaFuncSetAttribute(gm_main_kernel,
                         cudaFuncAttributeMaxDynamicSharedMemorySize, SMEM_BYTES);
    cudaFuncSetAttribute(gm_main_kernel,
                         cudaFuncAttributePreferredSharedMemoryCarveout, 100);
    gm_prep_kernel<<<1, 1024>>>(w, mu, A);
    gm_main_kernel<<<GRID_MAIN, THREADS, SMEM_BYTES>>>(sample, (float*)d_out);
}

// round 7
// speedup vs baseline: 1.5948x; 1.0034x over previous
#include <cuda_runtime.h>
#include <cstdint>

#define N_SAMPLES 131072
#define M_COMP    2048
#define NPAIR     (M_COMP/2)          // 1024 component pairs
#define THREADS   128
#define SPT       2
#define SAMPLES_PER_BLOCK (THREADS*SPT)                 // 256
#define GRID_MAIN (N_SAMPLES/SAMPLES_PER_BLOCK)         // 512
#define TILE      8
#define SMEM_BYTES (NPAIR * 3 * 16)   // 48 KB (general-path layout; fast uses 32 KB)

typedef unsigned long long ull;

// general path: per pair 12 floats [c0e,c0o,c1e,c1o | c2e,c2o,c3e,c3o | c4e,c4o,c5e,c5o] (x log2e)
__device__ float4 g_coef4[NPAIR * 3];
// fast path: per pair 8 floats [c3e,c3o, c4e,c4o, c5e,c5o, pad,pad] (x log2e)
__device__ float4 g_fastc[NPAIR * 2];
// L*g00, L*gs, L*g11 of component 0 (valid when uniform)
__device__ float  g_quad[4];
__device__ int    g_uniform;

// ---------- packed f32x2 helpers ----------
__device__ __forceinline__ ull pk2(float x) {
    ull r; asm("mov.b64 %0,{%1,%1};" : "=l"(r) : "f"(x)); return r;
}
__device__ __forceinline__ ull pk2p(float lo, float hi) {
    ull r; asm("mov.b64 %0,{%1,%2};" : "=l"(r) : "f"(lo), "f"(hi)); return r;
}
__device__ __forceinline__ void unpk(ull v, float& lo, float& hi) {
    asm("mov.b64 {%0,%1},%2;" : "=f"(lo), "=f"(hi) : "l"(v));
}
__device__ __forceinline__ ull f2fma(ull a, ull b, ull c) {
    ull d; asm("fma.rn.f32x2 %0,%1,%2,%3;" : "=l"(d) : "l"(a), "l"(b), "l"(c)); return d;
}
__device__ __forceinline__ ull f2add(ull a, ull b) {
    ull d; asm("add.rn.f32x2 %0,%1,%2;" : "=l"(d) : "l"(a), "l"(b)); return d;
}
__device__ __forceinline__ float ex2(float x) {
    float y; asm("ex2.approx.ftz.f32 %0,%1;" : "=f"(y) : "f"(x)); return y;
}
__device__ __forceinline__ float lg2(float x) {
    float y; asm("lg2.approx.f32 %0,%1;" : "=f"(y) : "f"(x)); return y;
}
__device__ __forceinline__ void lds2(ull& a, ull& b, uint32_t addr) {
    asm("ld.shared.v2.b64 {%0,%1},[%2];" : "=l"(a), "=l"(b) : "r"(addr));
}
__device__ __forceinline__ ull ldsb64(uint32_t addr) {
    ull a; asm("ld.shared.b64 %0,[%1];" : "=l"(a) : "r"(addr)); return a;
}

// ---------- prologue: logsumexp(w) + coefficients + uniformity flag ----------
__device__ __forceinline__ void write_coef(int m, float lse,
                                           const float* mu, const float* Am,
                                           float wm,
                                           float g000, float g010, float g110,
                                           int* flag) {
    float a00 = Am[4*m+0], a01 = Am[4*m+1], a10 = Am[4*m+2], a11 = Am[4*m+3];
    float g00 = 0.5f * (a00*a00 + a01*a01);
    float g01 = 0.5f * (a00*a10 + a01*a11);
    float g11 = 0.5f * (a10*a10 + a11*a11);
    if (!(g00 == g000 && g01 == g010 && g11 == g110))
        atomicAnd(flag, 0);
    float gs  = 2.0f * g01;
    float det = g00*g11 - g01*g01;
    float wl  = (wm - lse) + 0.5f * logf(det);
    float m0 = mu[2*m], m1 = mu[2*m+1];
    float c0 = -g00, c1 = -gs, c2 = -g11;
    float c3 = 2.0f*g00*m0 + gs*m1;
    float c4 = gs*m0 + 2.0f*g11*m1;
    float c5 = wl - (g00*m0*m0 + gs*m0*m1 + g11*m1*m1);
    const float L = 1.4426950408889634f; // log2(e)
    int p = m >> 1, off = (m & 1);
    float* o = (float*)g_coef4;
    int b = p * 12 + off;
    o[b + 0]  = c0 * L;
    o[b + 2]  = c1 * L;
    o[b + 4]  = c2 * L;
    o[b + 6]  = c3 * L;
    o[b + 8]  = c4 * L;
    o[b + 10] = c5 * L;
    float* f = (float*)g_fastc;
    int b2 = p * 8 + off;
    f[b2 + 0] = c3 * L;
    f[b2 + 2] = c4 * L;
    f[b2 + 4] = c5 * L;
}

__global__ void gm_prep_kernel(const float* __restrict__ w,
                               const float* __restrict__ mu,
                               const float* __restrict__ Am) {
    __shared__ float red[32];
    __shared__ float s_mx, s_lse;
    __shared__ int s_flag;
    int t = threadIdx.x;
    int lane = t & 31, wid = t >> 5;
    if (t == 0) s_flag = 1;

    float a = w[t], b = w[t + 1024];

    float v = fmaxf(a, b);
    #pragma unroll
    for (int o = 16; o; o >>= 1) v = fmaxf(v, __shfl_xor_sync(0xffffffffu, v, o));
    if (lane == 0) red[wid] = v;
    __syncthreads();
    if (wid == 0) {
        float m = red[lane];
        #pragma unroll
        for (int o = 16; o; o >>= 1) m = fmaxf(m, __shfl_xor_sync(0xffffffffu, m, o));
        if (lane == 0) s_mx = m;
    }
    __syncthreads();
    float mx = s_mx;

    float e = expf(a - mx) + expf(b - mx);
    #pragma unroll
    for (int o = 16; o; o >>= 1) e += __shfl_xor_sync(0xffffffffu, e, o);
    __syncthreads();
    if (lane == 0) red[wid] = e;
    __syncthreads();
    if (wid == 0) {
        float s = red[lane];
        #pragma unroll
        for (int o = 16; o; o >>= 1) s += __shfl_xor_sync(0xffffffffu, s, o);
        if (lane == 0) s_lse = mx + logf(s);
    }
    __syncthreads();
    float lse = s_lse;

    // component-0 reference G for uniformity check
    float r00 = Am[0], r01 = Am[1], r10 = Am[2], r11 = Am[3];
    float g000 = 0.5f * (r00*r00 + r01*r01);
    float g010 = 0.5f * (r00*r10 + r01*r11);
    float g110 = 0.5f * (r10*r10 + r11*r11);

    write_coef(t,        lse, mu, Am, a, g000, g010, g110, &s_flag);
    write_coef(t + 1024, lse, mu, Am, b, g000, g010, g110, &s_flag);
    __syncthreads();
    if (t == 0) {
        g_uniform = s_flag;
        const float L = 1.4426950408889634f;
        g_quad[0] = g000 * L;
        g_quad[1] = 2.0f * g010 * L;
        g_quad[2] = g110 * L;
    }
}

// ---------- main ----------
__global__ __launch_bounds__(THREADS, 4) void gm_main_kernel(
    const float* __restrict__ sample, float* __restrict__ out) {
    extern __shared__ float4 sc[];   // 48 KB dynamic (fast path uses 32 KB)
    const float LN2 = 0.6931471805599453f;

    int n0 = blockIdx.x * SAMPLES_PER_BLOCK + threadIdx.x;
    int n1 = n0 + THREADS;
    const float2* sp = (const float2*)sample;
    float2 pa = sp[n0];
    float2 pb = sp[n1];

    int uni = g_uniform;   // grid-uniform branch

    if (uni) {
        // ================= FAST PATH: uniform covariance =================
        #pragma unroll 1
        for (int i = threadIdx.x; i < NPAIR * 2; i += THREADS)
            sc[i] = g_fastc[i];
        __syncthreads();
        uint32_t sbase = (uint32_t)__cvta_generic_to_shared(sc);

        float q00 = g_quad[0], qs = g_quad[1], q11 = g_quad[2];
        // per-sample constants (log2 domain): K = -(g00 x0^2 + gs x0 x1 + g11 x1^2)*L
        float KA = -(q00*pa.x*pa.x + qs*pa.x*pa.y + q11*pa.y*pa.y);
        float KB = -(q00*pb.x*pb.x + qs*pb.x*pb.y + q11*pb.y*pb.y);

        ull AX0 = pk2(pa.x), AX1 = pk2(pa.y);
        ull BX0 = pk2(pb.x), BX1 = pk2(pb.y);

        float ma0 = -3.0e38f, ma1 = -3.0e38f, mb0 = -3.0e38f, mb1 = -3.0e38f;
        ull SA = 0ull, SB = 0ull;

        for (int t = 0; t < NPAIR; t += TILE) {
            ull va[TILE], vb[TILE];
            float ta0 = -3.0e38f, ta1 = -3.0e38f, tb0 = -3.0e38f, tb1 = -3.0e38f;
            uint32_t base = sbase + (uint32_t)t * 32u;
            #pragma unroll
            for (int i = 0; i < TILE; ++i) {
                uint32_t a = base + (uint32_t)i * 32u;
                ull U0, U1;
                lds2(U0, U1, a);
                ull U2 = ldsb64(a + 16u);
                va[i] = f2fma(AX0, U0, f2fma(AX1, U1, U2));
                vb[i] = f2fma(BX0, U0, f2fma(BX1, U1, U2));
                float x, y;
                unpk(va[i], x, y); ta0 = fmaxf(ta0, x); ta1 = fmaxf(ta1, y);
                unpk(vb[i], x, y); tb0 = fmaxf(tb0, x); tb1 = fmaxf(tb1, y);
            }
            float na0 = fmaxf(ma0, ta0), na1 = fmaxf(ma1, ta1);
            float nb0 = fmaxf(mb0, tb0), nb1 = fmaxf(mb1, tb1);
            ull RA  = pk2p(ex2(ma0 - na0), ex2(ma1 - na1));
            ull RB  = pk2p(ex2(mb0 - nb0), ex2(mb1 - nb1));
            ull NMA = pk2p(-na0, -na1);
            ull NMB = pk2p(-nb0, -nb1);
            ull TSA = 0ull, TSB = 0ull;
            #pragma unroll
            for (int i = 0; i < TILE; ++i) {
                ull da = f2add(va[i], NMA);
                ull db = f2add(vb[i], NMB);
                float x, y;
                unpk(da, x, y);
                TSA = f2add(TSA, pk2p(ex2(x), ex2(y)));
                unpk(db, x, y);
                TSB = f2add(TSB, pk2p(ex2(x), ex2(y)));
            }
            SA = f2fma(SA, RA, TSA);
            SB = f2fma(SB, RB, TSB);
            ma0 = na0; ma1 = na1; mb0 = nb0; mb1 = nb1;
        }

        float s0, s1;
        unpk(SA, s0, s1);
        {
            float M = fmaxf(ma0, ma1);
            float tot = s0 * ex2(ma0 - M) + s1 * ex2(ma1 - M);
            out[n0] = (KA + M + lg2(tot)) * LN2;
        }
        unpk(SB, s0, s1);
        {
            float M = fmaxf(mb0, mb1);
            float tot = s0 * ex2(mb0 - M) + s1 * ex2(mb1 - M);
            out[n1] = (KB + M + lg2(tot)) * LN2;
        }
    } else {
        // ================= GENERAL PATH (round-5, proven) =================
        #pragma unroll 1
        for (int i = threadIdx.x; i < NPAIR * 3; i += THREADS)
            sc[i] = g_coef4[i];
        __syncthreads();
        uint32_t sbase = (uint32_t)__cvta_generic_to_shared(sc);

        ull AF0 = pk2(pa.x * pa.x), AF1 = pk2(pa.x * pa.y), AF2 = pk2(pa.y * pa.y);
        ull AX0 = pk2(pa.x), AX1 = pk2(pa.y);
        ull BF0 = pk2(pb.x * pb.x), BF1 = pk2(pb.x * pb.y), BF2 = pk2(pb.y * pb.y);
        ull BX0 = pk2(pb.x), BX1 = pk2(pb.y);

        float ma0 = -3.0e38f, ma1 = -3.0e38f, mb0 = -3.0e38f, mb1 = -3.0e38f;
        ull SA = 0ull, SB = 0ull;

        for (int t = 0; t < NPAIR; t += TILE) {
            ull va[TILE], vb[TILE];
            float ta0 = -3.0e38f, ta1 = -3.0e38f, tb0 = -3.0e38f, tb1 = -3.0e38f;
            uint32_t base = sbase + (uint32_t)t * 48u;
            #pragma unroll
            for (int i = 0; i < TILE; ++i) {
                uint32_t a = base + (uint32_t)i * 48u;
                ull C0, C1, C2, C3, C4, C5;
                lds2(C0, C1, a);
                lds2(C2, C3, a + 16u);
                lds2(C4, C5, a + 32u);
                va[i] = f2fma(AF0, C0, f2fma(AF1, C1, f2fma(AF2, C2,
                        f2fma(AX0, C3, f2fma(AX1, C4, C5)))));
                vb[i] = f2fma(BF0, C0, f2fma(BF1, C1, f2fma(BF2, C2,
                        f2fma(BX0, C3, f2fma(BX1, C4, C5)))));
                float x, y;
                unpk(va[i], x, y); ta0 = fmaxf(ta0, x); ta1 = fmaxf(ta1, y);
                unpk(vb[i], x, y); tb0 = fmaxf(tb0, x); tb1 = fmaxf(tb1, y);
            }
            float na0 = fmaxf(ma0, ta0), na1 = fmaxf(ma1, ta1);
            float nb0 = fmaxf(mb0, tb0), nb1 = fmaxf(mb1, tb1);
            ull RA  = pk2p(ex2(ma0 - na0), ex2(ma1 - na1));
            ull RB  = pk2p(ex2(mb0 - nb0), ex2(mb1 - nb1));
            ull NMA = pk2p(-na0, -na1);
            ull NMB = pk2p(-nb0, -nb1);
            ull TSA = 0ull, TSB = 0ull;
            #pragma unroll
            for (int i = 0; i < TILE; ++i) {
                ull da = f2add(va[i], NMA);
                ull db = f2add(vb[i], NMB);
                float x, y;
                unpk(da, x, y);
                TSA = f2add(TSA, pk2p(ex2(x), ex2(y)));
                unpk(db, x, y);
                TSB = f2add(TSB, pk2p(ex2(x), ex2(y)));
            }
            SA = f2fma(SA, RA, TSA);
            SB = f2fma(SB, RB, TSB);
            ma0 = na0; ma1 = na1; mb0 = nb0; mb1 = nb1;
        }

        float s0, s1;
        unpk(SA, s0, s1);
        {
            float M = fmaxf(ma0, ma1);
            float tot = s0 * ex2(ma0 - M) + s1 * ex2(ma1 - M);
            out[n0] = (M + lg2(tot)) * LN2;
        }
        unpk(SB, s0, s1);
        {
            float M = fmaxf(mb0, mb1);
            float tot = s0 * ex2(mb0 - M) + s1 * ex2(mb1 - M);
            out[n1] = (M + lg2(tot)) * LN2;
        }
    }
}

extern "C" void kernel_launch(void* const* d_in, const int* in_sizes, int n_in,
                              void* d_out, int out_size) {
    const float *sample = nullptr, *mu = nullptr, *A = nullptr, *w = nullptr;
    for (int i = 0; i < n_in; ++i) {
        int sz = in_sizes[i];
        const float* p = (const float*)d_in[i];
        if      (sz == N_SAMPLES * 2) sample = p;
        else if (sz == M_COMP * 2)    mu = p;
        else if (sz == M_COMP * 4)    A = p;
        else if (sz == M_COMP)        w = p;
    }
    cudaFuncSetAttribute(gm_main_kernel,
                         cudaFuncAttributeMaxDynamicSharedMemorySize, SMEM_BYTES);
    cudaFuncSetAttribute(gm_main_kernel,
                         cudaFuncAttributePreferredSharedMemoryCarveout, 100);
    gm_prep_kernel<<<1, 1024>>>(w, mu, A);
    gm_main_kernel<<<GRID_MAIN, THREADS, SMEM_BYTES>>>(sample, (float*)d_out);
}